// round 1
// baseline (speedup 1.0000x reference)
#include <cuda_runtime.h>
#include <math.h>

// Problem constants (fixed shapes per reference)
#define NN   50000
#define EE   800000
#define GG   64
#define HH   4
#define DD   64
#define HDIM 256   // HH*DD

// ---------------- scratch (static device memory; no allocs) ----------------
__device__ __align__(16) float g_xl[NN * HDIM];
__device__ __align__(16) float g_xr[NN * HDIM];
__device__ __align__(16) float g_h1[NN * HDIM];
__device__ __align__(16) float g_h2[NN * HDIM];
__device__ __align__(16) float g_ee[EE * HH];
__device__ __align__(16) float g_den[NN * HH];
__device__ __align__(16) float g_cnt[GG];

// ---------------- GEMM: C[M,256] = A[M,K] @ W[K,256] + bias ----------------
// 64x64 block tile, 4x4 per thread, BK=16, 256 threads.
__global__ void gemm_bias_kernel(const float* __restrict__ A,
                                 const float* __restrict__ W,
                                 const float* __restrict__ bias,
                                 float* __restrict__ C,
                                 int M, int K) {
    __shared__ float As[16][64];   // [k][row]
    __shared__ float Ws[16][64];   // [k][col]

    const int t  = threadIdx.x;
    const int tx = t & 15;         // 0..15 -> 4 cols each
    const int ty = t >> 4;         // 0..15 -> 4 rows each
    const int rowBase = blockIdx.y * 64;
    const int colBase = blockIdx.x * 64;

    // A tile load mapping: 64 rows x 16 k -> one float4 per thread
    const int aRow = t >> 2;       // 0..63
    const int aVec = t & 3;        // 0..3  (k-chunk of 4)
    // W tile load mapping: 16 k x 64 cols -> one float4 per thread
    const int wRow = t >> 4;       // 0..15
    const int wVec = t & 15;       // 0..15 (col-chunk of 4)

    float acc[4][4];
    #pragma unroll
    for (int i = 0; i < 4; i++)
        #pragma unroll
        for (int j = 0; j < 4; j++) acc[i][j] = 0.0f;

    for (int k0 = 0; k0 < K; k0 += 16) {
        float4 av = make_float4(0.f, 0.f, 0.f, 0.f);
        const int gr = rowBase + aRow;
        if (gr < M) av = *(const float4*)&A[(size_t)gr * K + k0 + aVec * 4];
        As[aVec * 4 + 0][aRow] = av.x;
        As[aVec * 4 + 1][aRow] = av.y;
        As[aVec * 4 + 2][aRow] = av.z;
        As[aVec * 4 + 3][aRow] = av.w;

        float4 wv = *(const float4*)&W[(size_t)(k0 + wRow) * HDIM + colBase + wVec * 4];
        *(float4*)&Ws[wRow][wVec * 4] = wv;

        __syncthreads();
        #pragma unroll
        for (int k = 0; k < 16; k++) {
            float4 a4 = *(const float4*)&As[k][ty * 4];
            float4 w4 = *(const float4*)&Ws[k][tx * 4];
            float a[4] = {a4.x, a4.y, a4.z, a4.w};
            float w[4] = {w4.x, w4.y, w4.z, w4.w};
            #pragma unroll
            for (int i = 0; i < 4; i++)
                #pragma unroll
                for (int j = 0; j < 4; j++)
                    acc[i][j] = fmaf(a[i], w[j], acc[i][j]);
        }
        __syncthreads();
    }

    #pragma unroll
    for (int i = 0; i < 4; i++) {
        const int r = rowBase + ty * 4 + i;
        if (r < M) {
            #pragma unroll
            for (int j = 0; j < 4; j++) {
                const int c = colBase + tx * 4 + j;
                C[(size_t)r * HDIM + c] = acc[i][j] + bias[c];
            }
        }
    }
}

// ---------------- elementwise helpers ----------------
__global__ void set_bias_kernel(float* __restrict__ out, const float* __restrict__ bias) {
    int i = blockIdx.x * blockDim.x + threadIdx.x;
    if (i < NN * HDIM) out[i] = bias[i & (HDIM - 1)];
}

__global__ void zero_kernel(float* __restrict__ p, int n) {
    int i = blockIdx.x * blockDim.x + threadIdx.x;
    if (i < n) p[i] = 0.0f;
}

__global__ void silu_kernel(float* __restrict__ p, int n) {
    int i = blockIdx.x * blockDim.x + threadIdx.x;
    if (i < n) {
        float v = p[i];
        p[i] = v / (1.0f + expf(-v));
    }
}

// ---------------- edge pass 1: scores + softmax denominator ----------------
// One warp per edge. Softmax max-subtraction omitted (logits are O(1), exp safe;
// mathematically identical normalization).
__global__ void edge_score_kernel(const int* __restrict__ ei,
                                  const float* __restrict__ xl,
                                  const float* __restrict__ xr,
                                  const float* __restrict__ att,
                                  float* __restrict__ ee,
                                  float* __restrict__ den) {
    const int warp = (blockIdx.x * blockDim.x + threadIdx.x) >> 5;
    const int lane = threadIdx.x & 31;
    if (warp >= EE) return;
    const int src = ei[warp];
    const int dst = ei[EE + warp];
    const float* __restrict__ xls = xl + (size_t)src * HDIM;
    const float* __restrict__ xrd = xr + (size_t)dst * HDIM;

    float acc[HH];
    #pragma unroll
    for (int h = 0; h < HH; h++) {
        float s0 = xls[h * 64 + lane]      + xrd[h * 64 + lane];
        float s1 = xls[h * 64 + 32 + lane] + xrd[h * 64 + 32 + lane];
        s0 = s0 > 0.f ? s0 : 0.2f * s0;   // leaky_relu 0.2
        s1 = s1 > 0.f ? s1 : 0.2f * s1;
        acc[h] = fmaf(s0, __ldg(&att[h * 64 + lane]),
                      s1 * __ldg(&att[h * 64 + 32 + lane]));
    }
    #pragma unroll
    for (int h = 0; h < HH; h++) {
        float v = acc[h];
        #pragma unroll
        for (int o = 16; o > 0; o >>= 1) v += __shfl_xor_sync(0xFFFFFFFFu, v, o);
        acc[h] = v;
    }
    if (lane < HH) {
        float myv = acc[0];
        if (lane == 1) myv = acc[1];
        else if (lane == 2) myv = acc[2];
        else if (lane == 3) myv = acc[3];
        float e = expf(myv);
        ee[warp * HH + lane] = e;
        atomicAdd(&den[dst * HH + lane], e);
    }
}

// ---------------- edge pass 2: weighted aggregation ----------------
// One warp per edge; float4 atomics into out[dst].
__global__ void edge_aggr_kernel(const int* __restrict__ ei,
                                 const float* __restrict__ xl,
                                 const float* __restrict__ ee,
                                 const float* __restrict__ den,
                                 float* __restrict__ out) {
    const int warp = (blockIdx.x * blockDim.x + threadIdx.x) >> 5;
    const int lane = threadIdx.x & 31;
    if (warp >= EE) return;
    const int src = ei[warp];
    const int dst = ei[EE + warp];

    const float4 e4 = *(const float4*)&ee[warp * 4];
    const float4 d4 = *(const float4*)&den[dst * 4];
    const float a0 = e4.x / (d4.x + 1e-16f);
    const float a1 = e4.y / (d4.y + 1e-16f);
    const float a2 = e4.z / (d4.z + 1e-16f);
    const float a3 = e4.w / (d4.w + 1e-16f);

    const int head = lane >> 3;           // 8 lanes per head (8 floats each)
    float al = a0;
    if (head == 1) al = a1;
    else if (head == 2) al = a2;
    else if (head == 3) al = a3;

    const float4* __restrict__ xs = (const float4*)(xl + (size_t)src * HDIM);
    float4* o = (float4*)(out + (size_t)dst * HDIM);
    const int i0 = lane * 2;              // float4 index (0..63)

    float4 v = xs[i0];
    v.x *= al; v.y *= al; v.z *= al; v.w *= al;
    atomicAdd(&o[i0], v);
    float4 v2 = xs[i0 + 1];
    v2.x *= al; v2.y *= al; v2.z *= al; v2.w *= al;
    atomicAdd(&o[i0 + 1], v2);
}

// ---------------- global mean pool ----------------
__global__ void pool_acc_kernel(const float* __restrict__ h,
                                const int* __restrict__ batch,
                                float* __restrict__ out,
                                float* __restrict__ cnt) {
    int i = blockIdx.x * blockDim.x + threadIdx.x;   // over NN*64 float4 slots
    if (i >= NN * 64) return;
    const int n = i >> 6;
    const int c4 = i & 63;
    const int b = batch[n];
    float4 v = ((const float4*)(h + (size_t)n * HDIM))[c4];
    atomicAdd(&((float4*)(out + (size_t)b * HDIM))[c4], v);
    if (c4 == 0) atomicAdd(&cnt[b], 1.0f);
}

__global__ void pool_div_kernel(float* __restrict__ out, const float* __restrict__ cnt) {
    int i = blockIdx.x * blockDim.x + threadIdx.x;
    if (i < GG * HDIM) out[i] = out[i] / fmaxf(cnt[i >> 8], 1.0f);
}

// ---------------- launch ----------------
extern "C" void kernel_launch(void* const* d_in, const int* in_sizes, int n_in,
                              void* d_out, int out_size) {
    const float* x     = (const float*)d_in[0];
    const int*   ei    = (const int*)  d_in[1];
    const int*   batch = (const int*)  d_in[2];
    const float* Wl1   = (const float*)d_in[3];
    const float* bl1   = (const float*)d_in[4];
    const float* Wr1   = (const float*)d_in[5];
    const float* br1   = (const float*)d_in[6];
    const float* att1  = (const float*)d_in[7];
    const float* bias1 = (const float*)d_in[8];
    const float* Wl2   = (const float*)d_in[9];
    const float* bl2   = (const float*)d_in[10];
    const float* Wr2   = (const float*)d_in[11];
    const float* br2   = (const float*)d_in[12];
    const float* att2  = (const float*)d_in[13];
    const float* bias2 = (const float*)d_in[14];
    float* out = (float*)d_out;

    float *xl, *xr, *h1, *h2, *eeb, *den, *cnt;
    cudaGetSymbolAddress((void**)&xl,  g_xl);
    cudaGetSymbolAddress((void**)&xr,  g_xr);
    cudaGetSymbolAddress((void**)&h1,  g_h1);
    cudaGetSymbolAddress((void**)&h2,  g_h2);
    cudaGetSymbolAddress((void**)&eeb, g_ee);
    cudaGetSymbolAddress((void**)&den, g_den);
    cudaGetSymbolAddress((void**)&cnt, g_cnt);

    const dim3 ggrid(HDIM / 64, (NN + 63) / 64);
    const int nb  = (NN * HDIM + 255) / 256;
    const int eb  = (EE + 7) / 8;                 // 8 warps per 256-thread block
    const int dnb = (NN * HH + 255) / 256;

    // ---- layer 1 ----
    gemm_bias_kernel<<<ggrid, 256>>>(x, Wl1, bl1, xl, NN, 128);
    gemm_bias_kernel<<<ggrid, 256>>>(x, Wr1, br1, xr, NN, 128);
    set_bias_kernel<<<nb, 256>>>(h1, bias1);
    zero_kernel<<<dnb, 256>>>(den, NN * HH);
    edge_score_kernel<<<eb, 256>>>(ei, xl, xr, att1, eeb, den);
    edge_aggr_kernel<<<eb, 256>>>(ei, xl, eeb, den, h1);
    silu_kernel<<<nb, 256>>>(h1, NN * HDIM);

    // ---- layer 2 ----
    gemm_bias_kernel<<<ggrid, 256>>>(h1, Wl2, bl2, xl, NN, 256);
    gemm_bias_kernel<<<ggrid, 256>>>(h1, Wr2, br2, xr, NN, 256);
    set_bias_kernel<<<nb, 256>>>(h2, bias2);
    zero_kernel<<<dnb, 256>>>(den, NN * HH);
    edge_score_kernel<<<eb, 256>>>(ei, xl, xr, att2, eeb, den);
    edge_aggr_kernel<<<eb, 256>>>(ei, xl, eeb, den, h2);

    // ---- global mean pool ----
    zero_kernel<<<(GG * HDIM + 255) / 256, 256>>>(out, GG * HDIM);
    zero_kernel<<<1, GG>>>(cnt, GG);
    pool_acc_kernel<<<(NN * 64 + 255) / 256, 256>>>(h2, batch, out, cnt);
    pool_div_kernel<<<(GG * HDIM + 255) / 256, 256>>>(out, cnt);
}

// round 2
// speedup vs baseline: 1.6240x; 1.6240x over previous
#include <cuda_runtime.h>
#include <math.h>

// Problem constants (fixed shapes per reference)
#define NN   50000
#define EE   800000
#define GG   64
#define HH   4
#define DD   64
#define HDIM 256   // HH*DD

// ---------------- scratch (static device memory; no allocs) ----------------
__device__ __align__(16) float g_xl[NN * HDIM];
__device__ __align__(16) float g_xr[NN * HDIM];
__device__ __align__(16) float g_h1[NN * HDIM];
__device__ __align__(16) float g_h2[NN * HDIM];
__device__ __align__(16) float g_den[NN * HH];
__device__ __align__(16) float g_cnt[GG];

// ---------------- packed f32x2 helpers ----------------
__device__ __forceinline__ unsigned long long fma2(unsigned long long a,
                                                   unsigned long long b,
                                                   unsigned long long c) {
    unsigned long long d;
    asm("fma.rn.f32x2 %0, %1, %2, %3;" : "=l"(d) : "l"(a), "l"(b), "l"(c));
    return d;
}
__device__ __forceinline__ unsigned long long dup2(float x) {
    unsigned long long d;
    asm("mov.b64 %0, {%1, %1};" : "=l"(d) : "r"(__float_as_uint(x)));
    return d;
}
__device__ __forceinline__ void unpack2(unsigned long long v, float& lo, float& hi) {
    unsigned int a, b;
    asm("mov.b64 {%0, %1}, %2;" : "=r"(a), "=r"(b) : "l"(v));
    lo = __uint_as_float(a);
    hi = __uint_as_float(b);
}

// ---------------- fused dual GEMM ----------------
// Computes C0 = A@W0 + b0 and C1 = A@W1 + b1 in one launch (combined N=512).
// BM=128, BN=128, BK=16, 256 threads, 8x8 microtile, fp32x2 packed FMA.
__global__ void __launch_bounds__(256, 2)
gemm2_kernel(const float* __restrict__ A,
             const float* __restrict__ W0, const float* __restrict__ W1,
             const float* __restrict__ b0, const float* __restrict__ b1,
             float* __restrict__ C0, float* __restrict__ C1,
             int M, int K) {
    __shared__ float As[16][128];   // [k][row], 8KB
    __shared__ float Ws[16][128];   // [k][col], 8KB

    const int t  = threadIdx.x;
    const int tx = t & 15;          // 0..15 -> 8 cols each
    const int ty = t >> 4;          // 0..15 -> 8 rows each
    const int rowBase = blockIdx.y * 128;
    const int colBase = blockIdx.x * 128;       // 0..511

    const float* __restrict__ W    = (colBase < 256) ? W0 : W1;
    const float* __restrict__ bias = (colBase < 256) ? b0 : b1;
    float* __restrict__ C          = (colBase < 256) ? C0 : C1;
    const int wcolBase = colBase & 255;

    // preload bias for this thread's 8 columns
    float bloc[8];
    #pragma unroll
    for (int u = 0; u < 8; u++) bloc[u] = bias[wcolBase + tx * 8 + u];

    unsigned long long acc2[8][4];
    #pragma unroll
    for (int i = 0; i < 8; i++)
        #pragma unroll
        for (int j = 0; j < 4; j++) acc2[i][j] = 0ull;

    // A-tile load mapping: 512 float4 slots, thread handles slots t, t+256
    // W-tile load mapping: same
    for (int k0 = 0; k0 < K; k0 += 16) {
        #pragma unroll
        for (int half = 0; half < 2; half++) {
            const int s   = t + half * 256;
            const int row = s >> 2;        // 0..127
            const int kv  = s & 3;         // 0..3
            float4 av = make_float4(0.f, 0.f, 0.f, 0.f);
            const int gr = rowBase + row;
            if (gr < M) av = *(const float4*)&A[(size_t)gr * K + k0 + kv * 4];
            As[kv * 4 + 0][row] = av.x;
            As[kv * 4 + 1][row] = av.y;
            As[kv * 4 + 2][row] = av.z;
            As[kv * 4 + 3][row] = av.w;

            const int wr = s >> 5;         // 0..15
            const int wc = s & 31;         // 0..31
            float4 wv = *(const float4*)&W[(size_t)(k0 + wr) * HDIM + wcolBase + wc * 4];
            *(float4*)&Ws[wr][wc * 4] = wv;
        }
        __syncthreads();

        #pragma unroll
        for (int k = 0; k < 16; k++) {
            const float4 a0 = *(const float4*)&As[k][ty * 8];
            const float4 a1 = *(const float4*)&As[k][ty * 8 + 4];
            const longlong2 wA = *(const longlong2*)&Ws[k][tx * 8];
            const longlong2 wB = *(const longlong2*)&Ws[k][tx * 8 + 4];
            unsigned long long w2[4] = {(unsigned long long)wA.x, (unsigned long long)wA.y,
                                        (unsigned long long)wB.x, (unsigned long long)wB.y};
            const float a[8] = {a0.x, a0.y, a0.z, a0.w, a1.x, a1.y, a1.z, a1.w};
            #pragma unroll
            for (int i = 0; i < 8; i++) {
                const unsigned long long ad = dup2(a[i]);
                #pragma unroll
                for (int j = 0; j < 4; j++)
                    acc2[i][j] = fma2(ad, w2[j], acc2[i][j]);
            }
        }
        __syncthreads();
    }

    #pragma unroll
    for (int i = 0; i < 8; i++) {
        const int r = rowBase + ty * 8 + i;
        if (r < M) {
            float o[8];
            #pragma unroll
            for (int j = 0; j < 4; j++) {
                unpack2(acc2[i][j], o[2 * j], o[2 * j + 1]);
                o[2 * j]     += bloc[2 * j];
                o[2 * j + 1] += bloc[2 * j + 1];
            }
            float* crow = C + (size_t)r * HDIM + wcolBase + tx * 8;
            *(float4*)&crow[0] = make_float4(o[0], o[1], o[2], o[3]);
            *(float4*)&crow[4] = make_float4(o[4], o[5], o[6], o[7]);
        }
    }
}

// ---------------- fused edge pass ----------------
// One warp per edge. Computes e = exp(att . leaky(xl[src]+xr[dst])) per head,
// accumulates e*xl[src] into h[dst] and e into den[dst] (normalization is
// deferred to the node-level kernel; divisor is common so math is identical).
__global__ void edge_fused_kernel(const int* __restrict__ ei,
                                  const float* __restrict__ xl,
                                  const float* __restrict__ xr,
                                  const float* __restrict__ att,
                                  float* __restrict__ hout,
                                  float* __restrict__ den) {
    const int warp = (blockIdx.x * blockDim.x + threadIdx.x) >> 5;
    const int lane = threadIdx.x & 31;
    if (warp >= EE) return;
    const int src = ei[warp];
    const int dst = ei[EE + warp];

    const float4* __restrict__ xs = (const float4*)(xl + (size_t)src * HDIM);
    const float4* __restrict__ xd = (const float4*)(xr + (size_t)dst * HDIM);

    // lane holds float4 slots `lane` (head = lane>>4 in {0,1}) and
    // `lane+32` (head = 2 + (lane>>4) in {2,3})
    const float4 l0 = xs[lane];
    const float4 l1 = xs[lane + 32];
    const float4 r0 = xd[lane];
    const float4 r1 = xd[lane + 32];
    const float4 a0 = __ldg(&((const float4*)att)[lane]);
    const float4 a1 = __ldg(&((const float4*)att)[lane + 32]);

    float4 s0, s1;
    s0.x = l0.x + r0.x; s0.y = l0.y + r0.y; s0.z = l0.z + r0.z; s0.w = l0.w + r0.w;
    s1.x = l1.x + r1.x; s1.y = l1.y + r1.y; s1.z = l1.z + r1.z; s1.w = l1.w + r1.w;
    s0.x = s0.x > 0.f ? s0.x : 0.2f * s0.x;
    s0.y = s0.y > 0.f ? s0.y : 0.2f * s0.y;
    s0.z = s0.z > 0.f ? s0.z : 0.2f * s0.z;
    s0.w = s0.w > 0.f ? s0.w : 0.2f * s0.w;
    s1.x = s1.x > 0.f ? s1.x : 0.2f * s1.x;
    s1.y = s1.y > 0.f ? s1.y : 0.2f * s1.y;
    s1.z = s1.z > 0.f ? s1.z : 0.2f * s1.z;
    s1.w = s1.w > 0.f ? s1.w : 0.2f * s1.w;

    float p0 = s0.x * a0.x + s0.y * a0.y + s0.z * a0.z + s0.w * a0.w;
    float p1 = s1.x * a1.x + s1.y * a1.y + s1.z * a1.z + s1.w * a1.w;

    // reduce within the 16-lane group (xor offsets <= 8 stay in-group)
    #pragma unroll
    for (int o = 8; o > 0; o >>= 1) {
        p0 += __shfl_xor_sync(0xFFFFFFFFu, p0, o);
        p1 += __shfl_xor_sync(0xFFFFFFFFu, p1, o);
    }
    // group g = lane>>4: p0 = score(head g), p1 = score(head 2+g)
    const float eL = expf(p0);
    const float eH = expf(p1);

    float4 v0, v1;
    v0.x = l0.x * eL; v0.y = l0.y * eL; v0.z = l0.z * eL; v0.w = l0.w * eL;
    v1.x = l1.x * eH; v1.y = l1.y * eH; v1.z = l1.z * eH; v1.w = l1.w * eH;

    float4* ho = (float4*)(hout + (size_t)dst * HDIM);
    atomicAdd(&ho[lane], v0);
    atomicAdd(&ho[lane + 32], v1);

    if ((lane & 15) == 0) {          // lanes 0, 16
        const int g = lane >> 4;
        atomicAdd(&den[dst * HH + g], eL);
        atomicAdd(&den[dst * HH + 2 + g], eH);
    }
}

// ---------------- node-level normalize (+bias, optional silu) ----------------
template <bool SILU>
__global__ void norm_bias_kernel(float* __restrict__ h,
                                 const float* __restrict__ den,
                                 const float* __restrict__ bias) {
    int i = blockIdx.x * blockDim.x + threadIdx.x;   // over NN*64 float4 slots
    if (i >= NN * 64) return;
    const int n  = i >> 6;
    const int c4 = i & 63;
    const int hd = c4 >> 4;
    const float inv = 1.0f / (den[n * HH + hd] + 1e-16f);
    float4 v = ((float4*)h)[i];
    const float4 b = ((const float4*)bias)[c4];
    v.x = v.x * inv + b.x;
    v.y = v.y * inv + b.y;
    v.z = v.z * inv + b.z;
    v.w = v.w * inv + b.w;
    if (SILU) {
        v.x = v.x / (1.0f + expf(-v.x));
        v.y = v.y / (1.0f + expf(-v.y));
        v.z = v.z / (1.0f + expf(-v.z));
        v.w = v.w / (1.0f + expf(-v.w));
    }
    ((float4*)h)[i] = v;
}

// ---------------- global mean pool ----------------
__global__ void pool_acc_kernel(const float* __restrict__ h,
                                const int* __restrict__ batch,
                                float* __restrict__ out,
                                float* __restrict__ cnt) {
    int i = blockIdx.x * blockDim.x + threadIdx.x;   // over NN*64 float4 slots
    if (i >= NN * 64) return;
    const int n  = i >> 6;
    const int c4 = i & 63;
    const int b  = batch[n];
    float4 v = ((const float4*)(h + (size_t)n * HDIM))[c4];
    atomicAdd(&((float4*)(out + (size_t)b * HDIM))[c4], v);
    if (c4 == 0) atomicAdd(&cnt[b], 1.0f);
}

__global__ void pool_div_kernel(float* __restrict__ out, const float* __restrict__ cnt) {
    int i = blockIdx.x * blockDim.x + threadIdx.x;
    if (i < GG * HDIM) out[i] = out[i] / fmaxf(cnt[i >> 8], 1.0f);
}

// ---------------- launch ----------------
extern "C" void kernel_launch(void* const* d_in, const int* in_sizes, int n_in,
                              void* d_out, int out_size) {
    const float* x     = (const float*)d_in[0];
    const int*   ei    = (const int*)  d_in[1];
    const int*   batch = (const int*)  d_in[2];
    const float* Wl1   = (const float*)d_in[3];
    const float* bl1   = (const float*)d_in[4];
    const float* Wr1   = (const float*)d_in[5];
    const float* br1   = (const float*)d_in[6];
    const float* att1  = (const float*)d_in[7];
    const float* bias1 = (const float*)d_in[8];
    const float* Wl2   = (const float*)d_in[9];
    const float* bl2   = (const float*)d_in[10];
    const float* Wr2   = (const float*)d_in[11];
    const float* br2   = (const float*)d_in[12];
    const float* att2  = (const float*)d_in[13];
    const float* bias2 = (const float*)d_in[14];
    float* out = (float*)d_out;

    float *xl, *xr, *h1, *h2, *den, *cnt;
    cudaGetSymbolAddress((void**)&xl,  g_xl);
    cudaGetSymbolAddress((void**)&xr,  g_xr);
    cudaGetSymbolAddress((void**)&h1,  g_h1);
    cudaGetSymbolAddress((void**)&h2,  g_h2);
    cudaGetSymbolAddress((void**)&den, g_den);
    cudaGetSymbolAddress((void**)&cnt, g_cnt);

    const dim3 ggrid(4, (NN + 127) / 128);          // combined N=512
    const int nb4 = (NN * 64 + 255) / 256;          // float4-granular node kernels
    const int eb  = (EE + 7) / 8;                   // 8 warps per 256-thread block

    // ---- layer 1 ----
    gemm2_kernel<<<ggrid, 256>>>(x, Wl1, Wr1, bl1, br1, xl, xr, NN, 128);
    cudaMemsetAsync(h1, 0, (size_t)NN * HDIM * sizeof(float));
    cudaMemsetAsync(den, 0, (size_t)NN * HH * sizeof(float));
    edge_fused_kernel<<<eb, 256>>>(ei, xl, xr, att1, h1, den);
    norm_bias_kernel<true><<<nb4, 256>>>(h1, den, bias1);

    // ---- layer 2 ----
    gemm2_kernel<<<ggrid, 256>>>(h1, Wl2, Wr2, bl2, br2, xl, xr, NN, 256);
    cudaMemsetAsync(h2, 0, (size_t)NN * HDIM * sizeof(float));
    cudaMemsetAsync(den, 0, (size_t)NN * HH * sizeof(float));
    edge_fused_kernel<<<eb, 256>>>(ei, xl, xr, att2, h2, den);
    norm_bias_kernel<false><<<nb4, 256>>>(h2, den, bias2);

    // ---- global mean pool ----
    cudaMemsetAsync(out, 0, (size_t)GG * HDIM * sizeof(float));
    cudaMemsetAsync(cnt, 0, (size_t)GG * sizeof(float));
    pool_acc_kernel<<<nb4, 256>>>(h2, batch, out, cnt);
    pool_div_kernel<<<(GG * HDIM + 255) / 256, 256>>>(out, cnt);
}

// round 3
// speedup vs baseline: 2.1175x; 1.3038x over previous
#include <cuda_runtime.h>
#include <math.h>

// Problem constants (fixed shapes per reference)
#define NN   50000
#define EE   800000
#define GG   64
#define HH   4
#define DD   64
#define HDIM 256   // HH*DD
#define NB_SCAN ((NN + 1023) / 1024)   // 49 scan blocks

// ---------------- scratch (static device memory; no allocs) ----------------
__device__ __align__(16) float g_xl[NN * HDIM];
__device__ __align__(16) float g_xr[NN * HDIM];
__device__ __align__(16) float g_h1[NN * HDIM];
__device__ __align__(16) float g_h2[NN * HDIM];
__device__ __align__(16) float g_cnt[GG];
__device__ int g_deg[NN];
__device__ int g_fill[NN];
__device__ int g_rowptr[NN + 1];
__device__ int g_col[EE];
__device__ int g_partial[NB_SCAN];

// ---------------- packed f32x2 helpers ----------------
__device__ __forceinline__ unsigned long long fma2(unsigned long long a,
                                                   unsigned long long b,
                                                   unsigned long long c) {
    unsigned long long d;
    asm("fma.rn.f32x2 %0, %1, %2, %3;" : "=l"(d) : "l"(a), "l"(b), "l"(c));
    return d;
}
__device__ __forceinline__ unsigned long long dup2(float x) {
    unsigned long long d;
    asm("mov.b64 %0, {%1, %1};" : "=l"(d) : "r"(__float_as_uint(x)));
    return d;
}
__device__ __forceinline__ void unpack2(unsigned long long v, float& lo, float& hi) {
    unsigned int a, b;
    asm("mov.b64 {%0, %1}, %2;" : "=r"(a), "=r"(b) : "l"(v));
    lo = __uint_as_float(a);
    hi = __uint_as_float(b);
}

// ---------------- fused dual GEMM ----------------
// C0 = A@W0 + b0 and C1 = A@W1 + b1 in one launch (combined N=512).
// BM=128, BN=128, BK=16, 256 threads, 8x8 microtile, fp32x2 packed FMA.
__global__ void __launch_bounds__(256, 2)
gemm2_kernel(const float* __restrict__ A,
             const float* __restrict__ W0, const float* __restrict__ W1,
             const float* __restrict__ b0, const float* __restrict__ b1,
             float* __restrict__ C0, float* __restrict__ C1,
             int M, int K) {
    __shared__ float As[16][128];
    __shared__ float Ws[16][128];

    const int t  = threadIdx.x;
    const int tx = t & 15;
    const int ty = t >> 4;
    const int rowBase = blockIdx.y * 128;
    const int colBase = blockIdx.x * 128;

    const float* __restrict__ W    = (colBase < 256) ? W0 : W1;
    const float* __restrict__ bias = (colBase < 256) ? b0 : b1;
    float* __restrict__ C          = (colBase < 256) ? C0 : C1;
    const int wcolBase = colBase & 255;

    float bloc[8];
    #pragma unroll
    for (int u = 0; u < 8; u++) bloc[u] = bias[wcolBase + tx * 8 + u];

    unsigned long long acc2[8][4];
    #pragma unroll
    for (int i = 0; i < 8; i++)
        #pragma unroll
        for (int j = 0; j < 4; j++) acc2[i][j] = 0ull;

    for (int k0 = 0; k0 < K; k0 += 16) {
        #pragma unroll
        for (int half = 0; half < 2; half++) {
            const int s   = t + half * 256;
            const int row = s >> 2;
            const int kv  = s & 3;
            float4 av = make_float4(0.f, 0.f, 0.f, 0.f);
            const int gr = rowBase + row;
            if (gr < M) av = *(const float4*)&A[(size_t)gr * K + k0 + kv * 4];
            As[kv * 4 + 0][row] = av.x;
            As[kv * 4 + 1][row] = av.y;
            As[kv * 4 + 2][row] = av.z;
            As[kv * 4 + 3][row] = av.w;

            const int wr = s >> 5;
            const int wc = s & 31;
            float4 wv = *(const float4*)&W[(size_t)(k0 + wr) * HDIM + wcolBase + wc * 4];
            *(float4*)&Ws[wr][wc * 4] = wv;
        }
        __syncthreads();

        #pragma unroll
        for (int k = 0; k < 16; k++) {
            const float4 a0 = *(const float4*)&As[k][ty * 8];
            const float4 a1 = *(const float4*)&As[k][ty * 8 + 4];
            const longlong2 wA = *(const longlong2*)&Ws[k][tx * 8];
            const longlong2 wB = *(const longlong2*)&Ws[k][tx * 8 + 4];
            unsigned long long w2[4] = {(unsigned long long)wA.x, (unsigned long long)wA.y,
                                        (unsigned long long)wB.x, (unsigned long long)wB.y};
            const float a[8] = {a0.x, a0.y, a0.z, a0.w, a1.x, a1.y, a1.z, a1.w};
            #pragma unroll
            for (int i = 0; i < 8; i++) {
                const unsigned long long ad = dup2(a[i]);
                #pragma unroll
                for (int j = 0; j < 4; j++)
                    acc2[i][j] = fma2(ad, w2[j], acc2[i][j]);
            }
        }
        __syncthreads();
    }

    #pragma unroll
    for (int i = 0; i < 8; i++) {
        const int r = rowBase + ty * 8 + i;
        if (r < M) {
            float o[8];
            #pragma unroll
            for (int j = 0; j < 4; j++) {
                unpack2(acc2[i][j], o[2 * j], o[2 * j + 1]);
                o[2 * j]     += bloc[2 * j];
                o[2 * j + 1] += bloc[2 * j + 1];
            }
            float* crow = C + (size_t)r * HDIM + wcolBase + tx * 8;
            *(float4*)&crow[0] = make_float4(o[0], o[1], o[2], o[3]);
            *(float4*)&crow[4] = make_float4(o[4], o[5], o[6], o[7]);
        }
    }
}

// ---------------- CSR build ----------------
__global__ void deg_kernel(const int* __restrict__ ei, int* __restrict__ deg) {
    int e = blockIdx.x * blockDim.x + threadIdx.x;
    if (e < EE) atomicAdd(&deg[ei[EE + e]], 1);
}

// 1024 elements per block of 256 threads; per-thread serial 4 + Hillis-Steele.
__global__ void scan_block_kernel(const int* __restrict__ deg,
                                  int* __restrict__ excl,
                                  int* __restrict__ partial) {
    __shared__ int tsum[256];
    const int base = blockIdx.x * 1024;
    const int idx0 = base + threadIdx.x * 4;
    int v[4], pre[4];
    #pragma unroll
    for (int j = 0; j < 4; j++) v[j] = (idx0 + j < NN) ? deg[idx0 + j] : 0;
    int run = 0;
    #pragma unroll
    for (int j = 0; j < 4; j++) { pre[j] = run; run += v[j]; }
    tsum[threadIdx.x] = run;
    __syncthreads();
    #pragma unroll
    for (int off = 1; off < 256; off <<= 1) {
        int tv = (threadIdx.x >= off) ? tsum[threadIdx.x - off] : 0;
        __syncthreads();
        tsum[threadIdx.x] += tv;
        __syncthreads();
    }
    const int tOff = (threadIdx.x > 0) ? tsum[threadIdx.x - 1] : 0;
    #pragma unroll
    for (int j = 0; j < 4; j++)
        if (idx0 + j < NN) excl[idx0 + j] = tOff + pre[j];
    if (threadIdx.x == 255) partial[blockIdx.x] = tsum[255];
}

__global__ void scan_partial_kernel(int* __restrict__ partial) {
    if (threadIdx.x == 0) {
        int run = 0;
        for (int i = 0; i < NB_SCAN; i++) { int t = partial[i]; partial[i] = run; run += t; }
    }
}

__global__ void add_offset_kernel(int* __restrict__ rowptr, const int* __restrict__ partial) {
    int i = blockIdx.x * blockDim.x + threadIdx.x;
    if (i < NN) rowptr[i] += partial[i >> 10];
    if (i == 0) rowptr[NN] = EE;
}

__global__ void scatter_kernel(const int* __restrict__ ei,
                               const int* __restrict__ rowptr,
                               int* __restrict__ fill,
                               int* __restrict__ col) {
    int e = blockIdx.x * blockDim.x + threadIdx.x;
    if (e >= EE) return;
    const int dst = ei[EE + e];
    const int p = atomicAdd(&fill[dst], 1);
    col[rowptr[dst] + p] = ei[e];
}

// ---------------- node-major fused GATv2 aggregation ----------------
// One warp per dst node. xr[dst], att, accumulators, den live in registers;
// loop gathers xl[src] per in-edge (software-pipelined). Normalization + bias
// (+silu) fused at the end; h written exactly once, no atomics anywhere.
template <bool SILU>
__global__ void node_aggr_kernel(const int* __restrict__ rowptr,
                                 const int* __restrict__ col,
                                 const float* __restrict__ xl,
                                 const float* __restrict__ xr,
                                 const float* __restrict__ att,
                                 const float* __restrict__ bias,
                                 float* __restrict__ hout) {
    const int node = (blockIdx.x * blockDim.x + threadIdx.x) >> 5;
    const int lane = threadIdx.x & 31;
    if (node >= NN) return;

    const float4* __restrict__ xd = (const float4*)(xr + (size_t)node * HDIM);
    const float4 r0 = xd[lane];
    const float4 r1 = xd[lane + 32];
    const float4 a0 = __ldg(&((const float4*)att)[lane]);
    const float4 a1 = __ldg(&((const float4*)att)[lane + 32]);

    float4 acc0 = make_float4(0.f, 0.f, 0.f, 0.f);
    float4 acc1 = make_float4(0.f, 0.f, 0.f, 0.f);
    float denL = 0.f, denH = 0.f;

    const int pBeg = rowptr[node];
    const int pEnd = rowptr[node + 1];

    float4 l0n, l1n;
    if (pBeg < pEnd) {
        const float4* xs = (const float4*)(xl + (size_t)col[pBeg] * HDIM);
        l0n = xs[lane];
        l1n = xs[lane + 32];
    }

    for (int p = pBeg; p < pEnd; p++) {
        const float4 l0 = l0n;
        const float4 l1 = l1n;
        if (p + 1 < pEnd) {                         // prefetch next src row
            const float4* xs = (const float4*)(xl + (size_t)col[p + 1] * HDIM);
            l0n = xs[lane];
            l1n = xs[lane + 32];
        }

        float4 s0, s1;
        s0.x = l0.x + r0.x; s0.y = l0.y + r0.y; s0.z = l0.z + r0.z; s0.w = l0.w + r0.w;
        s1.x = l1.x + r1.x; s1.y = l1.y + r1.y; s1.z = l1.z + r1.z; s1.w = l1.w + r1.w;
        s0.x = s0.x > 0.f ? s0.x : 0.2f * s0.x;
        s0.y = s0.y > 0.f ? s0.y : 0.2f * s0.y;
        s0.z = s0.z > 0.f ? s0.z : 0.2f * s0.z;
        s0.w = s0.w > 0.f ? s0.w : 0.2f * s0.w;
        s1.x = s1.x > 0.f ? s1.x : 0.2f * s1.x;
        s1.y = s1.y > 0.f ? s1.y : 0.2f * s1.y;
        s1.z = s1.z > 0.f ? s1.z : 0.2f * s1.z;
        s1.w = s1.w > 0.f ? s1.w : 0.2f * s1.w;

        float p0 = s0.x * a0.x + s0.y * a0.y + s0.z * a0.z + s0.w * a0.w;
        float p1 = s1.x * a1.x + s1.y * a1.y + s1.z * a1.z + s1.w * a1.w;
        #pragma unroll
        for (int o = 8; o > 0; o >>= 1) {           // reduce within 16-lane group
            p0 += __shfl_xor_sync(0xFFFFFFFFu, p0, o);
            p1 += __shfl_xor_sync(0xFFFFFFFFu, p1, o);
        }
        // group g = lane>>4: p0 = score(head g), p1 = score(head 2+g)
        const float eL = __expf(p0);
        const float eH = __expf(p1);

        acc0.x = fmaf(l0.x, eL, acc0.x); acc0.y = fmaf(l0.y, eL, acc0.y);
        acc0.z = fmaf(l0.z, eL, acc0.z); acc0.w = fmaf(l0.w, eL, acc0.w);
        acc1.x = fmaf(l1.x, eH, acc1.x); acc1.y = fmaf(l1.y, eH, acc1.y);
        acc1.z = fmaf(l1.z, eH, acc1.z); acc1.w = fmaf(l1.w, eH, acc1.w);
        denL += eL;
        denH += eH;
    }

    const float invL = 1.0f / (denL + 1e-16f);
    const float invH = 1.0f / (denH + 1e-16f);
    const float4 b0 = __ldg(&((const float4*)bias)[lane]);
    const float4 b1 = __ldg(&((const float4*)bias)[lane + 32]);

    float4 o0, o1;
    o0.x = acc0.x * invL + b0.x; o0.y = acc0.y * invL + b0.y;
    o0.z = acc0.z * invL + b0.z; o0.w = acc0.w * invL + b0.w;
    o1.x = acc1.x * invH + b1.x; o1.y = acc1.y * invH + b1.y;
    o1.z = acc1.z * invH + b1.z; o1.w = acc1.w * invH + b1.w;
    if (SILU) {
        o0.x = o0.x / (1.0f + __expf(-o0.x));
        o0.y = o0.y / (1.0f + __expf(-o0.y));
        o0.z = o0.z / (1.0f + __expf(-o0.z));
        o0.w = o0.w / (1.0f + __expf(-o0.w));
        o1.x = o1.x / (1.0f + __expf(-o1.x));
        o1.y = o1.y / (1.0f + __expf(-o1.y));
        o1.z = o1.z / (1.0f + __expf(-o1.z));
        o1.w = o1.w / (1.0f + __expf(-o1.w));
    }
    float4* ho = (float4*)(hout + (size_t)node * HDIM);
    ho[lane]      = o0;
    ho[lane + 32] = o1;
}

// ---------------- global mean pool ----------------
__global__ void pool_acc_kernel(const float* __restrict__ h,
                                const int* __restrict__ batch,
                                float* __restrict__ out,
                                float* __restrict__ cnt) {
    int i = blockIdx.x * blockDim.x + threadIdx.x;   // over NN*64 float4 slots
    if (i >= NN * 64) return;
    const int n  = i >> 6;
    const int c4 = i & 63;
    const int b  = batch[n];
    float4 v = ((const float4*)(h + (size_t)n * HDIM))[c4];
    atomicAdd(&((float4*)(out + (size_t)b * HDIM))[c4], v);
    if (c4 == 0) atomicAdd(&cnt[b], 1.0f);
}

__global__ void pool_div_kernel(float* __restrict__ out, const float* __restrict__ cnt) {
    int i = blockIdx.x * blockDim.x + threadIdx.x;
    if (i < GG * HDIM) out[i] = out[i] / fmaxf(cnt[i >> 8], 1.0f);
}

// ---------------- launch ----------------
extern "C" void kernel_launch(void* const* d_in, const int* in_sizes, int n_in,
                              void* d_out, int out_size) {
    const float* x     = (const float*)d_in[0];
    const int*   ei    = (const int*)  d_in[1];
    const int*   batch = (const int*)  d_in[2];
    const float* Wl1   = (const float*)d_in[3];
    const float* bl1   = (const float*)d_in[4];
    const float* Wr1   = (const float*)d_in[5];
    const float* br1   = (const float*)d_in[6];
    const float* att1  = (const float*)d_in[7];
    const float* bias1 = (const float*)d_in[8];
    const float* Wl2   = (const float*)d_in[9];
    const float* bl2   = (const float*)d_in[10];
    const float* Wr2   = (const float*)d_in[11];
    const float* br2   = (const float*)d_in[12];
    const float* att2  = (const float*)d_in[13];
    const float* bias2 = (const float*)d_in[14];
    float* out = (float*)d_out;

    float *xl, *xr, *h1, *h2, *cnt;
    int *deg, *fill, *rowptr, *colA, *partial;
    cudaGetSymbolAddress((void**)&xl,      g_xl);
    cudaGetSymbolAddress((void**)&xr,      g_xr);
    cudaGetSymbolAddress((void**)&h1,      g_h1);
    cudaGetSymbolAddress((void**)&h2,      g_h2);
    cudaGetSymbolAddress((void**)&cnt,     g_cnt);
    cudaGetSymbolAddress((void**)&deg,     g_deg);
    cudaGetSymbolAddress((void**)&fill,    g_fill);
    cudaGetSymbolAddress((void**)&rowptr,  g_rowptr);
    cudaGetSymbolAddress((void**)&colA,    g_col);
    cudaGetSymbolAddress((void**)&partial, g_partial);

    const dim3 ggrid(4, (NN + 127) / 128);
    const int nb4 = (NN * 64 + 255) / 256;
    const int ebE = (EE + 255) / 256;
    const int nwb = (NN * 32 + 255) / 256;          // one warp per node

    // ---- CSR build (used by both layers) ----
    cudaMemsetAsync(deg, 0, NN * sizeof(int));
    cudaMemsetAsync(fill, 0, NN * sizeof(int));
    deg_kernel<<<ebE, 256>>>(ei, deg);
    scan_block_kernel<<<NB_SCAN, 256>>>(deg, rowptr, partial);
    scan_partial_kernel<<<1, 32>>>(partial);
    add_offset_kernel<<<(NN + 255) / 256, 256>>>(rowptr, partial);
    scatter_kernel<<<ebE, 256>>>(ei, rowptr, fill, colA);

    // ---- layer 1 ----
    gemm2_kernel<<<ggrid, 256>>>(x, Wl1, Wr1, bl1, br1, xl, xr, NN, 128);
    node_aggr_kernel<true><<<nwb, 256>>>(rowptr, colA, xl, xr, att1, bias1, h1);

    // ---- layer 2 ----
    gemm2_kernel<<<ggrid, 256>>>(h1, Wl2, Wr2, bl2, br2, xl, xr, NN, 256);
    node_aggr_kernel<false><<<nwb, 256>>>(rowptr, colA, xl, xr, att2, bias2, h2);

    // ---- global mean pool ----
    cudaMemsetAsync(out, 0, (size_t)GG * HDIM * sizeof(float));
    cudaMemsetAsync(cnt, 0, (size_t)GG * sizeof(float));
    pool_acc_kernel<<<nb4, 256>>>(h2, batch, out, cnt);
    pool_div_kernel<<<(GG * HDIM + 255) / 256, 256>>>(out, cnt);
}

// round 5
// speedup vs baseline: 3.1862x; 1.5047x over previous
#include <cuda_runtime.h>
#include <cuda_bf16.h>
#include <math.h>
#include <stdint.h>

// Problem constants (fixed shapes per reference)
#define NN   50000
#define EE   800000
#define GG   64
#define HH   4
#define HDIM 256   // 4 heads * 64
#define NB_SCAN ((NN + 1023) / 1024)

// ---------------- scratch (static device memory; no allocs) ----------------
__device__ __align__(16) float g_xl[NN * HDIM];
__device__ __align__(16) float g_xr[NN * HDIM];
__device__ __align__(16) float g_h1[NN * HDIM];
__device__ __align__(16) float g_h2[NN * HDIM];
__device__ __align__(16) float g_cnt[GG];
__device__ int g_deg[NN];
__device__ int g_fill[NN];
__device__ int g_rowptr[NN + 1];
__device__ int g_col[EE];
__device__ int g_partial[NB_SCAN];

// ================= bf16 3-pass mma.sync GEMM =================
// Block tile 128x128, BK=32, 8 warps (warp tile m32 x n64).
// smem: A_hi/A_lo 128 rows x 32 bf16 (stride 80B, pad for conflict-free
// ldmatrix), B_hi/B_lo 32 k-rows x 128 bf16 (stride 272B).
#define ASTR 80
#define BSTR 272
#define OFF_AHI 0
#define OFF_ALO (128 * ASTR)                   // 10240
#define OFF_BHI (2 * 128 * ASTR)               // 20480
#define OFF_BLO (2 * 128 * ASTR + 32 * BSTR)   // 29184
#define SM_GEMM (2 * 128 * ASTR + 2 * 32 * BSTR)   // 37888 bytes

static __device__ __forceinline__ uint32_t smem_u32(const void* p) {
    uint32_t a;
    asm("{ .reg .u64 t; cvta.to.shared.u64 t, %1; cvt.u32.u64 %0, t; }"
        : "=r"(a) : "l"(p));
    return a;
}
static __device__ __forceinline__ unsigned short bf_us(float x) {
    __nv_bfloat16 h = __float2bfloat16_rn(x);
    return *(unsigned short*)&h;
}
static __device__ __forceinline__ float bf_f(unsigned short u) {
    __nv_bfloat16 h = *(__nv_bfloat16*)&u;
    return __bfloat162float(h);
}
// convert float4 -> (hi0|hi1, hi2|hi3) and same for residual lo
static __device__ __forceinline__ void cvt_hilo(float4 v, uint2& hi, uint2& lo) {
    unsigned short h0 = bf_us(v.x), h1 = bf_us(v.y), h2 = bf_us(v.z), h3 = bf_us(v.w);
    unsigned short l0 = bf_us(v.x - bf_f(h0));
    unsigned short l1 = bf_us(v.y - bf_f(h1));
    unsigned short l2 = bf_us(v.z - bf_f(h2));
    unsigned short l3 = bf_us(v.w - bf_f(h3));
    hi.x = (uint32_t)h0 | ((uint32_t)h1 << 16);
    hi.y = (uint32_t)h2 | ((uint32_t)h3 << 16);
    lo.x = (uint32_t)l0 | ((uint32_t)l1 << 16);
    lo.y = (uint32_t)l2 | ((uint32_t)l3 << 16);
}
static __device__ __forceinline__ void ldsm4(uint32_t addr, uint32_t* r) {
    asm volatile("ldmatrix.sync.aligned.m8n8.x4.shared.b16 {%0,%1,%2,%3}, [%4];"
                 : "=r"(r[0]), "=r"(r[1]), "=r"(r[2]), "=r"(r[3]) : "r"(addr));
}
static __device__ __forceinline__ void ldsm4t(uint32_t addr, uint32_t* r) {
    asm volatile("ldmatrix.sync.aligned.m8n8.x4.trans.shared.b16 {%0,%1,%2,%3}, [%4];"
                 : "=r"(r[0]), "=r"(r[1]), "=r"(r[2]), "=r"(r[3]) : "r"(addr));
}
static __device__ __forceinline__ void mma_bf16(float* d, const uint32_t* a,
                                                uint32_t b0, uint32_t b1) {
    asm volatile(
        "mma.sync.aligned.m16n8k16.row.col.f32.bf16.bf16.f32 "
        "{%0,%1,%2,%3}, {%4,%5,%6,%7}, {%8,%9}, {%0,%1,%2,%3};"
        : "+f"(d[0]), "+f"(d[1]), "+f"(d[2]), "+f"(d[3])
        : "r"(a[0]), "r"(a[1]), "r"(a[2]), "r"(a[3]), "r"(b0), "r"(b1));
}

// C0 = A@W0 + b0 (blockIdx.x<2) / C1 = A@W1 + b1 ; colBase=(x&1)*128
__global__ void __launch_bounds__(256, 2)
gemm_mma_kernel(const float* __restrict__ A,
                const float* __restrict__ W0, const float* __restrict__ W1,
                const float* __restrict__ b0, const float* __restrict__ b1,
                float* __restrict__ C0, float* __restrict__ C1,
                int M, int K) {
    __shared__ __align__(16) unsigned char smbuf[SM_GEMM];
    const uint32_t smb = smem_u32(smbuf);

    const int t    = threadIdx.x;
    const int lane = t & 31;
    const int wid  = t >> 5;
    const int wm   = wid & 3;          // 4 warps over M (32 rows each)
    const int wn   = wid >> 2;         // 2 warps over N (64 cols each)
    const int rowBase = blockIdx.y * 128;
    const int colW    = (blockIdx.x & 1) * 128;

    const float* __restrict__ Wm   = (blockIdx.x < 2) ? W0 : W1;
    const float* __restrict__ bias = (blockIdx.x < 2) ? b0 : b1;
    float* __restrict__ C          = (blockIdx.x < 2) ? C0 : C1;

    float acc[2][8][4];
    #pragma unroll
    for (int i = 0; i < 2; i++)
        #pragma unroll
        for (int j = 0; j < 8; j++)
            #pragma unroll
            for (int q = 0; q < 4; q++) acc[i][j][q] = 0.0f;

    for (int k0 = 0; k0 < K; k0 += 32) {
        // ---- fill A: 128 rows x 32 k (1024 float4 slots) ----
        #pragma unroll
        for (int i = 0; i < 4; i++) {
            const int slot = t + i * 256;
            const int row  = slot >> 3;
            const int kq   = slot & 7;
            const int gr   = rowBase + row;
            float4 v = make_float4(0.f, 0.f, 0.f, 0.f);
            if (gr < M) v = *(const float4*)&A[(size_t)gr * K + k0 + kq * 4];
            uint2 hi, lo;
            cvt_hilo(v, hi, lo);
            *(uint2*)(smbuf + OFF_AHI + row * ASTR + kq * 8) = hi;
            *(uint2*)(smbuf + OFF_ALO + row * ASTR + kq * 8) = lo;
        }
        // ---- fill B: 32 k-rows x 128 n (1024 float4 slots) ----
        #pragma unroll
        for (int i = 0; i < 4; i++) {
            const int slot = t + i * 256;
            const int row  = slot >> 5;
            const int c4   = slot & 31;
            float4 v = *(const float4*)&Wm[(size_t)(k0 + row) * HDIM + colW + c4 * 4];
            uint2 hi, lo;
            cvt_hilo(v, hi, lo);
            *(uint2*)(smbuf + OFF_BHI + row * BSTR + c4 * 8) = hi;
            *(uint2*)(smbuf + OFF_BLO + row * BSTR + c4 * 8) = lo;
        }
        __syncthreads();

        #pragma unroll
        for (int s = 0; s < 2; s++) {           // two k16 steps
            uint32_t ahi[2][4], alo[2][4];
            #pragma unroll
            for (int mt = 0; mt < 2; mt++) {
                const int row = wm * 32 + mt * 16 + (lane & 15);
                const uint32_t aoff = row * ASTR + (lane >> 4) * 16 + s * 32;
                ldsm4(smb + OFF_AHI + aoff, ahi[mt]);
                ldsm4(smb + OFF_ALO + aoff, alo[mt]);
            }
            #pragma unroll
            for (int np = 0; np < 4; np++) {    // pairs of n8 tiles
                const int g    = lane >> 3;
                const int krow = s * 16 + (g & 1) * 8 + (lane & 7);
                const int ncol = wn * 64 + np * 16 + (g >> 1) * 8;
                const uint32_t boff = krow * BSTR + ncol * 2;
                uint32_t bhi[4], blo[4];
                ldsm4t(smb + OFF_BHI + boff, bhi);
                ldsm4t(smb + OFF_BLO + boff, blo);
                #pragma unroll
                for (int mt = 0; mt < 2; mt++) {
                    #pragma unroll
                    for (int tt = 0; tt < 2; tt++) {
                        float* d = acc[mt][np * 2 + tt];
                        mma_bf16(d, ahi[mt], bhi[2 * tt], bhi[2 * tt + 1]);
                        mma_bf16(d, ahi[mt], blo[2 * tt], blo[2 * tt + 1]);
                        mma_bf16(d, alo[mt], bhi[2 * tt], bhi[2 * tt + 1]);
                    }
                }
            }
        }
        __syncthreads();
    }

    // ---- epilogue: acc + bias -> C ----
    #pragma unroll
    for (int mt = 0; mt < 2; mt++) {
        const int r0 = rowBase + wm * 32 + mt * 16 + (lane >> 2);
        #pragma unroll
        for (int nt = 0; nt < 8; nt++) {
            const int cg = colW + wn * 64 + nt * 8 + (lane & 3) * 2;
            const float2 bv = __ldg((const float2*)&bias[cg]);
            if (r0 < M) {
                float2 v = make_float2(acc[mt][nt][0] + bv.x, acc[mt][nt][1] + bv.y);
                *(float2*)&C[(size_t)r0 * HDIM + cg] = v;
            }
            if (r0 + 8 < M) {
                float2 v = make_float2(acc[mt][nt][2] + bv.x, acc[mt][nt][3] + bv.y);
                *(float2*)&C[(size_t)(r0 + 8) * HDIM + cg] = v;
            }
        }
    }
}

// ---------------- CSR build ----------------
__global__ void deg_kernel(const int* __restrict__ ei, int* __restrict__ deg) {
    int e = blockIdx.x * blockDim.x + threadIdx.x;
    if (e < EE) atomicAdd(&deg[ei[EE + e]], 1);
}

__global__ void scan_block_kernel(const int* __restrict__ deg,
                                  int* __restrict__ excl,
                                  int* __restrict__ partial) {
    __shared__ int tsum[256];
    const int base = blockIdx.x * 1024;
    const int idx0 = base + threadIdx.x * 4;
    int v[4], pre[4];
    #pragma unroll
    for (int j = 0; j < 4; j++) v[j] = (idx0 + j < NN) ? deg[idx0 + j] : 0;
    int run = 0;
    #pragma unroll
    for (int j = 0; j < 4; j++) { pre[j] = run; run += v[j]; }
    tsum[threadIdx.x] = run;
    __syncthreads();
    #pragma unroll
    for (int off = 1; off < 256; off <<= 1) {
        int tv = (threadIdx.x >= off) ? tsum[threadIdx.x - off] : 0;
        __syncthreads();
        tsum[threadIdx.x] += tv;
        __syncthreads();
    }
    const int tOff = (threadIdx.x > 0) ? tsum[threadIdx.x - 1] : 0;
    #pragma unroll
    for (int j = 0; j < 4; j++)
        if (idx0 + j < NN) excl[idx0 + j] = tOff + pre[j];
    if (threadIdx.x == 255) partial[blockIdx.x] = tsum[255];
}

__global__ void scan_partial_kernel(int* __restrict__ partial) {
    if (threadIdx.x == 0) {
        int run = 0;
        for (int i = 0; i < NB_SCAN; i++) { int t = partial[i]; partial[i] = run; run += t; }
    }
}

__global__ void add_offset_kernel(int* __restrict__ rowptr, const int* __restrict__ partial) {
    int i = blockIdx.x * blockDim.x + threadIdx.x;
    if (i < NN) rowptr[i] += partial[i >> 10];
    if (i == 0) rowptr[NN] = EE;
}

__global__ void scatter_kernel(const int* __restrict__ ei,
                               const int* __restrict__ rowptr,
                               int* __restrict__ fill,
                               int* __restrict__ col) {
    int e = blockIdx.x * blockDim.x + threadIdx.x;
    if (e >= EE) return;
    const int dst = ei[EE + e];
    const int p = atomicAdd(&fill[dst], 1);
    col[rowptr[dst] + p] = ei[e];
}

// ---------------- node-major fused GATv2 aggregation ----------------
template <bool SILU>
__global__ void node_aggr_kernel(const int* __restrict__ rowptr,
                                 const int* __restrict__ col,
                                 const float* __restrict__ xl,
                                 const float* __restrict__ xr,
                                 const float* __restrict__ att,
                                 const float* __restrict__ bias,
                                 float* __restrict__ hout) {
    const int node = (blockIdx.x * blockDim.x + threadIdx.x) >> 5;
    const int lane = threadIdx.x & 31;
    if (node >= NN) return;

    const float4* __restrict__ xd = (const float4*)(xr + (size_t)node * HDIM);
    const float4 r0 = xd[lane];
    const float4 r1 = xd[lane + 32];
    const float4 a0 = __ldg(&((const float4*)att)[lane]);
    const float4 a1 = __ldg(&((const float4*)att)[lane + 32]);

    float4 acc0 = make_float4(0.f, 0.f, 0.f, 0.f);
    float4 acc1 = make_float4(0.f, 0.f, 0.f, 0.f);
    float denL = 0.f, denH = 0.f;

    const int pBeg = rowptr[node];
    const int pEnd = rowptr[node + 1];

    float4 l0n, l1n;
    if (pBeg < pEnd) {
        const float4* xs = (const float4*)(xl + (size_t)col[pBeg] * HDIM);
        l0n = xs[lane];
        l1n = xs[lane + 32];
    }

    for (int p = pBeg; p < pEnd; p++) {
        const float4 l0 = l0n;
        const float4 l1 = l1n;
        if (p + 1 < pEnd) {
            const float4* xs = (const float4*)(xl + (size_t)col[p + 1] * HDIM);
            l0n = xs[lane];
            l1n = xs[lane + 32];
        }

        float4 s0, s1;
        s0.x = l0.x + r0.x; s0.y = l0.y + r0.y; s0.z = l0.z + r0.z; s0.w = l0.w + r0.w;
        s1.x = l1.x + r1.x; s1.y = l1.y + r1.y; s1.z = l1.z + r1.z; s1.w = l1.w + r1.w;
        s0.x = s0.x > 0.f ? s0.x : 0.2f * s0.x;
        s0.y = s0.y > 0.f ? s0.y : 0.2f * s0.y;
        s0.z = s0.z > 0.f ? s0.z : 0.2f * s0.z;
        s0.w = s0.w > 0.f ? s0.w : 0.2f * s0.w;
        s1.x = s1.x > 0.f ? s1.x : 0.2f * s1.x;
        s1.y = s1.y > 0.f ? s1.y : 0.2f * s1.y;
        s1.z = s1.z > 0.f ? s1.z : 0.2f * s1.z;
        s1.w = s1.w > 0.f ? s1.w : 0.2f * s1.w;

        float p0 = s0.x * a0.x + s0.y * a0.y + s0.z * a0.z + s0.w * a0.w;
        float p1 = s1.x * a1.x + s1.y * a1.y + s1.z * a1.z + s1.w * a1.w;
        #pragma unroll
        for (int o = 8; o > 0; o >>= 1) {
            p0 += __shfl_xor_sync(0xFFFFFFFFu, p0, o);
            p1 += __shfl_xor_sync(0xFFFFFFFFu, p1, o);
        }
        const float eL = __expf(p0);
        const float eH = __expf(p1);

        acc0.x = fmaf(l0.x, eL, acc0.x); acc0.y = fmaf(l0.y, eL, acc0.y);
        acc0.z = fmaf(l0.z, eL, acc0.z); acc0.w = fmaf(l0.w, eL, acc0.w);
        acc1.x = fmaf(l1.x, eH, acc1.x); acc1.y = fmaf(l1.y, eH, acc1.y);
        acc1.z = fmaf(l1.z, eH, acc1.z); acc1.w = fmaf(l1.w, eH, acc1.w);
        denL += eL;
        denH += eH;
    }

    const float invL = 1.0f / (denL + 1e-16f);
    const float invH = 1.0f / (denH + 1e-16f);
    const float4 b0 = __ldg(&((const float4*)bias)[lane]);
    const float4 b1 = __ldg(&((const float4*)bias)[lane + 32]);

    float4 o0, o1;
    o0.x = acc0.x * invL + b0.x; o0.y = acc0.y * invL + b0.y;
    o0.z = acc0.z * invL + b0.z; o0.w = acc0.w * invL + b0.w;
    o1.x = acc1.x * invH + b1.x; o1.y = acc1.y * invH + b1.y;
    o1.z = acc1.z * invH + b1.z; o1.w = acc1.w * invH + b1.w;
    if (SILU) {
        o0.x = o0.x / (1.0f + __expf(-o0.x));
        o0.y = o0.y / (1.0f + __expf(-o0.y));
        o0.z = o0.z / (1.0f + __expf(-o0.z));
        o0.w = o0.w / (1.0f + __expf(-o0.w));
        o1.x = o1.x / (1.0f + __expf(-o1.x));
        o1.y = o1.y / (1.0f + __expf(-o1.y));
        o1.z = o1.z / (1.0f + __expf(-o1.z));
        o1.w = o1.w / (1.0f + __expf(-o1.w));
    }
    float4* ho = (float4*)(hout + (size_t)node * HDIM);
    ho[lane]      = o0;
    ho[lane + 32] = o1;
}

// ---------------- global mean pool ----------------
__global__ void pool_acc_kernel(const float* __restrict__ h,
                                const int* __restrict__ batch,
                                float* __restrict__ out,
                                float* __restrict__ cnt) {
    int i = blockIdx.x * blockDim.x + threadIdx.x;
    if (i >= NN * 64) return;
    const int n  = i >> 6;
    const int c4 = i & 63;
    const int b  = batch[n];
    float4 v = ((const float4*)(h + (size_t)n * HDIM))[c4];
    atomicAdd(&((float4*)(out + (size_t)b * HDIM))[c4], v);
    if (c4 == 0) atomicAdd(&cnt[b], 1.0f);
}

__global__ void pool_div_kernel(float* __restrict__ out, const float* __restrict__ cnt) {
    int i = blockIdx.x * blockDim.x + threadIdx.x;
    if (i < GG * HDIM) out[i] = out[i] / fmaxf(cnt[i >> 8], 1.0f);
}

// ---------------- launch ----------------
extern "C" void kernel_launch(void* const* d_in, const int* in_sizes, int n_in,
                              void* d_out, int out_size) {
    const float* x     = (const float*)d_in[0];
    const int*   ei    = (const int*)  d_in[1];
    const int*   batch = (const int*)  d_in[2];
    const float* Wl1   = (const float*)d_in[3];
    const float* bl1   = (const float*)d_in[4];
    const float* Wr1   = (const float*)d_in[5];
    const float* br1   = (const float*)d_in[6];
    const float* att1  = (const float*)d_in[7];
    const float* bias1 = (const float*)d_in[8];
    const float* Wl2   = (const float*)d_in[9];
    const float* bl2   = (const float*)d_in[10];
    const float* Wr2   = (const float*)d_in[11];
    const float* br2   = (const float*)d_in[12];
    const float* att2  = (const float*)d_in[13];
    const float* bias2 = (const float*)d_in[14];
    float* out = (float*)d_out;

    float *xl, *xr, *h1, *h2, *cnt;
    int *deg, *fill, *rowptr, *colA, *partial;
    cudaGetSymbolAddress((void**)&xl,      g_xl);
    cudaGetSymbolAddress((void**)&xr,      g_xr);
    cudaGetSymbolAddress((void**)&h1,      g_h1);
    cudaGetSymbolAddress((void**)&h2,      g_h2);
    cudaGetSymbolAddress((void**)&cnt,     g_cnt);
    cudaGetSymbolAddress((void**)&deg,     g_deg);
    cudaGetSymbolAddress((void**)&fill,    g_fill);
    cudaGetSymbolAddress((void**)&rowptr,  g_rowptr);
    cudaGetSymbolAddress((void**)&colA,    g_col);
    cudaGetSymbolAddress((void**)&partial, g_partial);

    const dim3 ggrid(4, (NN + 127) / 128);
    const int nb4 = (NN * 64 + 255) / 256;
    const int ebE = (EE + 255) / 256;
    const int nwb = (NN * 32 + 255) / 256;

    // ---- CSR build (used by both layers) ----
    cudaMemsetAsync(deg, 0, NN * sizeof(int));
    cudaMemsetAsync(fill, 0, NN * sizeof(int));
    deg_kernel<<<ebE, 256>>>(ei, deg);
    scan_block_kernel<<<NB_SCAN, 256>>>(deg, rowptr, partial);
    scan_partial_kernel<<<1, 32>>>(partial);
    add_offset_kernel<<<(NN + 255) / 256, 256>>>(rowptr, partial);
    scatter_kernel<<<ebE, 256>>>(ei, rowptr, fill, colA);

    // ---- layer 1 ----
    gemm_mma_kernel<<<ggrid, 256>>>(x, Wl1, Wr1, bl1, br1, xl, xr, NN, 128);
    node_aggr_kernel<true><<<nwb, 256>>>(rowptr, colA, xl, xr, att1, bias1, h1);

    // ---- layer 2 ----
    gemm_mma_kernel<<<ggrid, 256>>>(h1, Wl2, Wr2, bl2, br2, xl, xr, NN, 256);
    node_aggr_kernel<false><<<nwb, 256>>>(rowptr, colA, xl, xr, att2, bias2, h2);

    // ---- global mean pool ----
    cudaMemsetAsync(out, 0, (size_t)GG * HDIM * sizeof(float));
    cudaMemsetAsync(cnt, 0, (size_t)GG * sizeof(float));
    pool_acc_kernel<<<nb4, 256>>>(h2, batch, out, cnt);
    pool_div_kernel<<<(GG * HDIM + 255) / 256, 256>>>(out, cnt);
}